// round 9
// baseline (speedup 1.0000x reference)
#include <cuda_runtime.h>
#include <cstdint>

#define B_   2
#define LQ   2048
#define LKV  2048
#define D    1024
#define NH   16
#define HD   64
#define MTOT (B_ * LQ)
#define LBH  (B_ * NH)
#define EPS  1e-5f
#define QSZ  4194304           // 4096*1024

// ---------------------------------------------------------------------------
// Scratch (static __device__, allocation-free).
// RULE (learned R3-R6): NEVER pass these as kernel arguments from host —
// host sees the shadow symbol, and GB300 ATS silently dereferences it.
// ---------------------------------------------------------------------------
__device__ float g_WTq[1048576], g_WTk[1048576], g_WTv[1048576], g_WTo[1048576];
__device__ float g_Q[QSZ], g_K[QSZ], g_V[QSZ];   // head-major projections
__device__ float g_ctx[QSZ];
__device__ float g_X[QSZ];

// ---------------------------------------------------------------------------
// helpers
// ---------------------------------------------------------------------------
__device__ __forceinline__ void cp16f(float* s, const float* g) {
    uint32_t sa;
    asm("{ .reg .u64 t; cvta.to.shared.u64 t, %1; cvt.u32.u64 %0, t; }"
        : "=r"(sa) : "l"(s));
    asm volatile("cp.async.cg.shared.global [%0], [%1], 16;" :: "r"(sa), "l"(g) : "memory");
}
#define CP_COMMIT()  asm volatile("cp.async.commit_group;" ::: "memory")
#define CP_WAIT0()   asm volatile("cp.async.wait_group 0;" ::: "memory")
#define CP_WAIT1()   asm volatile("cp.async.wait_group 1;" ::: "memory")

__device__ __forceinline__ uint32_t f2tf32(float f) {
    uint32_t u;
    asm("cvt.rna.tf32.f32 %0, %1;" : "=r"(u) : "f"(f));
    return u;
}

__device__ __forceinline__ void mma_tf32(float* c, uint32_t a0, uint32_t a1,
                                         uint32_t a2, uint32_t a3,
                                         uint32_t b0, uint32_t b1) {
    asm volatile(
        "mma.sync.aligned.m16n8k8.row.col.f32.tf32.tf32.f32 "
        "{%0,%1,%2,%3},{%4,%5,%6,%7},{%8,%9},{%0,%1,%2,%3};"
        : "+f"(c[0]), "+f"(c[1]), "+f"(c[2]), "+f"(c[3])
        : "r"(a0), "r"(a1), "r"(a2), "r"(a3), "r"(b0), "r"(b1));
}

// ---------------------------------------------------------------------------
// tf32 warp-MMA GEMM, 2-stage double-buffered cp.async pipeline.
// C[M,1024] = A[M,1024] @ W (via WT[N,K] scratch). Block 128x128, BK=32.
// Dynamic smem: 4 tiles of 128*TSTR floats (A0,A1,B0,B1) = 73728 B.
// ---------------------------------------------------------------------------
#define KK 1024
#define TSTR 36
#define TILEF (128 * TSTR)

template <int E>
__global__ __launch_bounds__(256, 1) void tgemm(
    const float* __restrict__ Ain,
    int sel, const float* __restrict__ bias, const float* __restrict__ resid)
{
    extern __shared__ float dsm[];
    float* bufA[2] = {dsm,             dsm + TILEF};
    float* bufB[2] = {dsm + 2 * TILEF, dsm + 3 * TILEF};

    const float* B = (sel == 0) ? g_WTq : (sel == 1) ? g_WTk
                   : (sel == 2) ? g_WTv : g_WTo;
    const float* A = (E == 1) ? g_ctx : Ain;

    const int tid  = threadIdx.x;
    const int lane = tid & 31;
    const int w    = tid >> 5;
    const int wm   = w & 1;
    const int wn   = w >> 1;
    const int m0 = blockIdx.y * 128, n0 = blockIdx.x * 128;

    float c[4][4][4];
#pragma unroll
    for (int i = 0; i < 4; i++)
#pragma unroll
        for (int j = 0; j < 4; j++)
#pragma unroll
            for (int q = 0; q < 4; q++) c[i][j][q] = 0.f;

    const int arow = wm * 64 + (lane >> 2);
    const int acol = lane & 3;
    const int brow = wn * 32 + (lane >> 2);

    auto stage = [&](int bi, int kb) {
#pragma unroll
        for (int i = 0; i < 4; i++) {
            int idx = tid + i * 256;
            int r = idx >> 3, ch = idx & 7;
            int so = r * TSTR + ch * 4;
            cp16f(bufA[bi] + so, A + (size_t)(m0 + r) * KK + kb + ch * 4);
            cp16f(bufB[bi] + so, B + (size_t)(n0 + r) * KK + kb + ch * 4);
        }
    };

    constexpr int nk = KK / 32;
    stage(0, 0);
    CP_COMMIT();

    for (int kt = 0; kt < nk; kt++) {
        if (kt + 1 < nk) {
            stage((kt + 1) & 1, (kt + 1) * 32);
            CP_COMMIT();
            CP_WAIT1();
        } else {
            CP_WAIT0();
        }
        __syncthreads();

        const float* sA = bufA[kt & 1];
        const float* sB = bufB[kt & 1];

#pragma unroll
        for (int ks = 0; ks < 4; ks++) {
            const int ko = ks * 8;
            uint32_t af[4][4], bf[4][2];
#pragma unroll
            for (int mf = 0; mf < 4; mf++) {
                int base = (arow + mf * 16) * TSTR + acol + ko;
                af[mf][0] = f2tf32(sA[base]);
                af[mf][1] = f2tf32(sA[base + 8 * TSTR]);
                af[mf][2] = f2tf32(sA[base + 4]);
                af[mf][3] = f2tf32(sA[base + 8 * TSTR + 4]);
            }
#pragma unroll
            for (int nf = 0; nf < 4; nf++) {
                int bb = (brow + nf * 8) * TSTR + acol + ko;
                bf[nf][0] = f2tf32(sB[bb]);
                bf[nf][1] = f2tf32(sB[bb + 4]);
            }
#pragma unroll
            for (int mf = 0; mf < 4; mf++)
#pragma unroll
                for (int nf = 0; nf < 4; nf++)
                    mma_tf32(c[mf][nf], af[mf][0], af[mf][1], af[mf][2], af[mf][3],
                             bf[nf][0], bf[nf][1]);
        }
        __syncthreads();   // buffer kt&1 free for stage kt+2
    }

#pragma unroll
    for (int mf = 0; mf < 4; mf++)
#pragma unroll
        for (int nf = 0; nf < 4; nf++)
#pragma unroll
            for (int half = 0; half < 2; half++) {
                int m = m0 + wm * 64 + mf * 16 + (lane >> 2) + half * 8;
                int n = n0 + wn * 32 + nf * 8 + (lane & 3) * 2;
                float2 v = make_float2(c[mf][nf][half * 2], c[mf][nf][half * 2 + 1]);

                if constexpr (E == 0) {
                    v.x += __ldg(&bias[n]); v.y += __ldg(&bias[n + 1]);
                    float* outp = (sel == 0) ? g_Q : (sel == 1) ? g_K : g_V;
                    size_t dst = (((size_t)((m >> 11) * NH + (n >> 6))) * LQ + (m & 2047)) * HD + (n & 63);
                    *(float2*)(outp + dst) = v;
                } else {
                    size_t idx = (size_t)m * D + n;
                    float2 r4 = *(const float2*)(resid + idx);
                    v.x += __ldg(&bias[n]) + r4.x;
                    v.y += __ldg(&bias[n + 1]) + r4.y;
                    *(float2*)(g_X + idx) = v;
                }
            }
}

// ---------------------------------------------------------------------------
// fp32 transpose for all 4 weights in one launch (blockIdx.z selects)
// ---------------------------------------------------------------------------
__global__ __launch_bounds__(256) void wtrans4(
    const float* __restrict__ Wq, const float* __restrict__ Wk,
    const float* __restrict__ Wv, const float* __restrict__ Wo)
{
    const int osel = blockIdx.z;
    const float* x = (osel == 0) ? Wq : (osel == 1) ? Wk : (osel == 2) ? Wv : Wo;
    float* y = (osel == 0) ? g_WTq : (osel == 1) ? g_WTk
             : (osel == 2) ? g_WTv : g_WTo;

    __shared__ float t[32][33];
    const int c0 = blockIdx.x * 32, r0 = blockIdx.y * 32;
    const int tx = threadIdx.x, ty = threadIdx.y;

#pragma unroll
    for (int i = 0; i < 4; i++)
        t[ty + 8 * i][tx] = x[(size_t)(r0 + ty + 8 * i) * KK + c0 + tx];
    __syncthreads();
#pragma unroll
    for (int i = 0; i < 4; i++)
        y[(size_t)(c0 + ty + 8 * i) * KK + r0 + tx] = t[tx][ty + 8 * i];
}

// ---------------------------------------------------------------------------
// Tensor-core flash attention (tf32), 2-stage double-buffered K/V pipeline.
// Block: 128 q-rows of one (b,h). 8 warps x 16 q-rows. KV tile = 64.
// Dynamic smem: sK x2 (stride 68) + sV x2 (stride 72) = 71680 B.
// ---------------------------------------------------------------------------
#define KSTR 68
#define VSTR 72
#define KTILE (64 * KSTR)
#define VTILE (64 * VSTR)

__global__ __launch_bounds__(256, 1) void attn_tc()
{
    extern __shared__ float asm_[];
    float* bufK[2] = {asm_,              asm_ + KTILE};
    float* bufV[2] = {asm_ + 2 * KTILE,  asm_ + 2 * KTILE + VTILE};

    const int bh = blockIdx.y;
    const int q0 = blockIdx.x * 128;
    const float* Qp = g_Q + (size_t)bh * LQ * HD;
    const float* Kp = g_K + (size_t)bh * LKV * HD;
    const float* Vp = g_V + (size_t)bh * LKV * HD;

    const int tid  = threadIdx.x;
    const int lane = tid & 31;
    const int w    = tid >> 5;
    const int qr   = lane >> 2;
    const int qc   = lane & 3;

    auto stageKV = [&](int bi, int kv0) {
#pragma unroll
        for (int i = 0; i < 4; i++) {
            int idx = tid + i * 256;
            int r = idx >> 4, ch = idx & 15;
            cp16f(bufK[bi] + r * KSTR + ch * 4, Kp + (size_t)(kv0 + r) * HD + ch * 4);
            cp16f(bufV[bi] + r * VSTR + ch * 4, Vp + (size_t)(kv0 + r) * HD + ch * 4);
        }
    };

    // ---- load Q fragments (16 rows per warp, 8 k-steps) ----
    uint32_t qf[8][4];
    {
        const int r0 = q0 + w * 16 + qr;
#pragma unroll
        for (int ks = 0; ks < 8; ks++) {
            int k = ks * 8 + qc;
            qf[ks][0] = f2tf32(__ldg(Qp + (size_t)r0 * HD + k));
            qf[ks][1] = f2tf32(__ldg(Qp + (size_t)(r0 + 8) * HD + k));
            qf[ks][2] = f2tf32(__ldg(Qp + (size_t)r0 * HD + k + 4));
            qf[ks][3] = f2tf32(__ldg(Qp + (size_t)(r0 + 8) * HD + k + 4));
        }
    }

    float o[8][4];
#pragma unroll
    for (int i = 0; i < 8; i++)
#pragma unroll
        for (int j = 0; j < 4; j++) o[i][j] = 0.f;
    float m_i[2] = {-1e30f, -1e30f};
    float l_i[2] = {0.f, 0.f};

    const int srcA = (lane & ~3) | (qc >> 1);
    const int srcB = srcA + 2;

    constexpr int nt = LKV / 64;
    stageKV(0, 0);
    CP_COMMIT();

    for (int t = 0; t < nt; t++) {
        if (t + 1 < nt) {
            stageKV((t + 1) & 1, (t + 1) * 64);
            CP_COMMIT();
            CP_WAIT1();
        } else {
            CP_WAIT0();
        }
        __syncthreads();

        const float* sK = bufK[t & 1];
        const float* sV = bufV[t & 1];

        // ---- S = Q K^T ----
        float s[8][4];
#pragma unroll
        for (int i = 0; i < 8; i++)
#pragma unroll
            for (int j = 0; j < 4; j++) s[i][j] = 0.f;

#pragma unroll
        for (int ks = 0; ks < 8; ks++) {
            const int ko = ks * 8;
#pragma unroll
            for (int nf = 0; nf < 8; nf++) {
                int bb = (nf * 8 + qr) * KSTR + ko + qc;
                uint32_t b0 = f2tf32(sK[bb]);
                uint32_t b1 = f2tf32(sK[bb + 4]);
                mma_tf32(s[nf], qf[ks][0], qf[ks][1], qf[ks][2], qf[ks][3], b0, b1);
            }
        }

        // ---- online softmax ----
        float mx0 = -1e30f, mx1 = -1e30f;
#pragma unroll
        for (int nf = 0; nf < 8; nf++) {
            s[nf][0] *= 0.125f; s[nf][1] *= 0.125f;
            s[nf][2] *= 0.125f; s[nf][3] *= 0.125f;
            mx0 = fmaxf(mx0, fmaxf(s[nf][0], s[nf][1]));
            mx1 = fmaxf(mx1, fmaxf(s[nf][2], s[nf][3]));
        }
        mx0 = fmaxf(mx0, __shfl_xor_sync(0xffffffffu, mx0, 1));
        mx0 = fmaxf(mx0, __shfl_xor_sync(0xffffffffu, mx0, 2));
        mx1 = fmaxf(mx1, __shfl_xor_sync(0xffffffffu, mx1, 1));
        mx1 = fmaxf(mx1, __shfl_xor_sync(0xffffffffu, mx1, 2));

        float mn0 = fmaxf(m_i[0], mx0), mn1 = fmaxf(m_i[1], mx1);
        float al0 = __expf(m_i[0] - mn0), al1 = __expf(m_i[1] - mn1);
        m_i[0] = mn0; m_i[1] = mn1;

        float rs0 = 0.f, rs1 = 0.f;
#pragma unroll
        for (int nf = 0; nf < 8; nf++) {
            s[nf][0] = __expf(s[nf][0] - mn0);
            s[nf][1] = __expf(s[nf][1] - mn0);
            s[nf][2] = __expf(s[nf][2] - mn1);
            s[nf][3] = __expf(s[nf][3] - mn1);
            rs0 += s[nf][0] + s[nf][1];
            rs1 += s[nf][2] + s[nf][3];
        }
        rs0 += __shfl_xor_sync(0xffffffffu, rs0, 1);
        rs0 += __shfl_xor_sync(0xffffffffu, rs0, 2);
        rs1 += __shfl_xor_sync(0xffffffffu, rs1, 1);
        rs1 += __shfl_xor_sync(0xffffffffu, rs1, 2);
        l_i[0] = l_i[0] * al0 + rs0;
        l_i[1] = l_i[1] * al1 + rs1;

#pragma unroll
        for (int nf = 0; nf < 8; nf++) {
            o[nf][0] *= al0; o[nf][1] *= al0;
            o[nf][2] *= al1; o[nf][3] *= al1;
        }

        // ---- O += P V (P re-laid via shuffles) ----
#pragma unroll
        for (int kg = 0; kg < 8; kg++) {
            uint32_t p0 = f2tf32(s[kg][0]), p1 = f2tf32(s[kg][1]);
            uint32_t p2 = f2tf32(s[kg][2]), p3 = f2tf32(s[kg][3]);
            uint32_t v0 = __shfl_sync(0xffffffffu, p0, srcA);
            uint32_t v1 = __shfl_sync(0xffffffffu, p1, srcA);
            uint32_t v2 = __shfl_sync(0xffffffffu, p2, srcA);
            uint32_t v3 = __shfl_sync(0xffffffffu, p3, srcA);
            uint32_t w0 = __shfl_sync(0xffffffffu, p0, srcB);
            uint32_t w1 = __shfl_sync(0xffffffffu, p1, srcB);
            uint32_t w2 = __shfl_sync(0xffffffffu, p2, srcB);
            uint32_t w3 = __shfl_sync(0xffffffffu, p3, srcB);
            uint32_t a0 = (qc & 1) ? v1 : v0;
            uint32_t a1 = (qc & 1) ? v3 : v2;
            uint32_t a2 = (qc & 1) ? w1 : w0;
            uint32_t a3 = (qc & 1) ? w3 : w2;

            const int ko = kg * 8;
#pragma unroll
            for (int nf = 0; nf < 8; nf++) {
                int bb = (ko + qc) * VSTR + nf * 8 + qr;
                uint32_t b0 = f2tf32(sV[bb]);
                uint32_t b1 = f2tf32(sV[bb + 4 * VSTR]);
                mma_tf32(o[nf], a0, a1, a2, a3, b0, b1);
            }
        }
        __syncthreads();   // buffers free for next stage
    }

    // ---- epilogue ----
    const int b = bh >> 4, h = bh & 15;
    const float inv0 = 1.0f / l_i[0], inv1 = 1.0f / l_i[1];
    const int r0 = q0 + w * 16 + qr;
#pragma unroll
    for (int nf = 0; nf < 8; nf++) {
        int col = h * HD + nf * 8 + qc * 2;
        float2 u0 = make_float2(o[nf][0] * inv0, o[nf][1] * inv0);
        float2 u1 = make_float2(o[nf][2] * inv1, o[nf][3] * inv1);
        *(float2*)(g_ctx + (size_t)(b * LQ + r0) * D + col)       = u0;
        *(float2*)(g_ctx + (size_t)(b * LQ + r0 + 8) * D + col)   = u1;
    }
}

// ---------------------------------------------------------------------------
// LayerNorm over last dim (1024)
// ---------------------------------------------------------------------------
__global__ __launch_bounds__(256) void ln_kernel(
    const float* __restrict__ gamma, const float* __restrict__ beta,
    float* __restrict__ out)
{
    __shared__ float red[8];
    const int row = blockIdx.x;
    const int t   = threadIdx.x;
    const float* x = g_X + (size_t)row * D;

    float4 xv = *(const float4*)&x[t << 2];
    float s = xv.x + xv.y + xv.z + xv.w;
#pragma unroll
    for (int m = 16; m > 0; m >>= 1) s += __shfl_xor_sync(0xffffffffu, s, m);
    if ((t & 31) == 0) red[t >> 5] = s;
    __syncthreads();
    float tot = 0.f;
#pragma unroll
    for (int i = 0; i < 8; i++) tot += red[i];
    float mu = tot * (1.0f / D);

    float d0 = xv.x - mu, d1 = xv.y - mu, d2 = xv.z - mu, d3 = xv.w - mu;
    float ss = d0 * d0 + d1 * d1 + d2 * d2 + d3 * d3;
#pragma unroll
    for (int m = 16; m > 0; m >>= 1) ss += __shfl_xor_sync(0xffffffffu, ss, m);
    __syncthreads();
    if ((t & 31) == 0) red[t >> 5] = ss;
    __syncthreads();
    float vtot = 0.f;
#pragma unroll
    for (int i = 0; i < 8; i++) vtot += red[i];
    float inv = rsqrtf(vtot * (1.0f / D) + EPS);

    float4 g  = *(const float4*)&gamma[t << 2];
    float4 be = *(const float4*)&beta[t << 2];
    float4 o;
    o.x = d0 * inv * g.x + be.x;
    o.y = d1 * inv * g.y + be.y;
    o.z = d2 * inv * g.z + be.z;
    o.w = d3 * inv * g.w + be.w;
    *(float4*)&out[(size_t)row * D + (t << 2)] = o;
}

// ---------------------------------------------------------------------------
extern "C" void kernel_launch(void* const* d_in, const int* in_sizes, int n_in,
                              void* d_out, int out_size)
{
    (void)in_sizes; (void)n_in; (void)out_size;
    const float* query     = (const float*)d_in[0];
    const float* key_value = (const float*)d_in[1];
    const float* Wq = (const float*)d_in[2];
    const float* bq = (const float*)d_in[3];
    const float* Wk = (const float*)d_in[4];
    const float* bk = (const float*)d_in[5];
    const float* Wv = (const float*)d_in[6];
    const float* bv = (const float*)d_in[7];
    const float* Wo = (const float*)d_in[8];
    const float* bo = (const float*)d_in[9];
    const float* gamma = (const float*)d_in[10];
    const float* beta  = (const float*)d_in[11];
    float* out = (float*)d_out;

    constexpr int GSM = 4 * TILEF * 4;                 // 73728 B
    constexpr int ASM = (2 * KTILE + 2 * VTILE) * 4;   // 71680 B
    cudaFuncSetAttribute(tgemm<0>, cudaFuncAttributeMaxDynamicSharedMemorySize, GSM);
    cudaFuncSetAttribute(tgemm<1>, cudaFuncAttributeMaxDynamicSharedMemorySize, GSM);
    cudaFuncSetAttribute(attn_tc,  cudaFuncAttributeMaxDynamicSharedMemorySize, ASM);

    // 1. transpose all weights (one launch)
    wtrans4<<<dim3(32, 32, 4), dim3(32, 8)>>>(Wq, Wk, Wv, Wo);

    // 2. Q/K/V projections (tf32 tensor cores, head-major fp32 out)
    dim3 pg(8, 32);
    tgemm<0><<<pg, 256, GSM>>>(query,     0, bq, nullptr);
    tgemm<0><<<pg, 256, GSM>>>(key_value, 1, bk, nullptr);
    tgemm<0><<<pg, 256, GSM>>>(key_value, 2, bv, nullptr);

    // 3. attention (tf32 tensor-core flash, double-buffered)
    attn_tc<<<dim3(LQ / 128, LBH), 256, ASM>>>();

    // 4. output projection + residual
    tgemm<1><<<pg, 256, GSM>>>(nullptr, 3, bo, query);

    // 5. LayerNorm
    ln_kernel<<<MTOT, 256>>>(gamma, beta, out);
}